// round 10
// baseline (speedup 1.0000x reference)
#include <cuda_runtime.h>
#include <math.h>

#define NNODES 50000
#define NEDGES 800000

// ---------------- scratch (device globals: allocation-free) ----------------
__device__ int   g_cnt[NNODES];
__device__ int   g_cursor[NNODES];
__device__ int   g_rowptr[NNODES + 1];
__device__ int   g_colp[NEDGES];
__device__ float g_simp[NEDGES];
__device__ float g_invn[NNODES];
__device__ float g_invrs[NNODES];
__device__ float g_wself[NNODES];
__device__ float g_z [NNODES * 256];
__device__ float g_h1[NNODES * 256];
__device__ float g_h2[NNODES * 256];
__device__ float g_B [256 * 256];

// ---------------- CSR build ----------------
__global__ void zero_cnt_kernel() {
    int i = blockIdx.x * blockDim.x + threadIdx.x;
    if (i < NNODES) g_cnt[i] = 0;
}

__global__ void hist_kernel(const int* __restrict__ row) {
    int e = blockIdx.x * blockDim.x + threadIdx.x;
    if (e < NEDGES) atomicAdd(&g_cnt[row[e]], 1);
}

__global__ void scan_kernel() {
    __shared__ int wsum[32];
    __shared__ int carry;
    int tid = threadIdx.x, lane = tid & 31, wid = tid >> 5;
    if (tid == 0) { carry = 0; g_rowptr[0] = 0; }
    __syncthreads();
    for (int base = 0; base < NNODES; base += 1024) {
        int i = base + tid;
        int v = (i < NNODES) ? g_cnt[i] : 0;
        int s = v;
        #pragma unroll
        for (int o = 1; o < 32; o <<= 1) {
            int t = __shfl_up_sync(0xffffffffu, s, o);
            if (lane >= o) s += t;
        }
        if (lane == 31) wsum[wid] = s;
        __syncthreads();
        if (wid == 0) {
            int ws = wsum[lane];
            #pragma unroll
            for (int o = 1; o < 32; o <<= 1) {
                int t = __shfl_up_sync(0xffffffffu, ws, o);
                if (lane >= o) ws += t;
            }
            wsum[lane] = ws;
        }
        __syncthreads();
        int incl = s + (wid ? wsum[wid - 1] : 0) + carry;
        if (i < NNODES) { g_rowptr[i + 1] = incl; g_cursor[i] = incl - v; }
        __syncthreads();
        if (tid == 1023) carry = incl;
        __syncthreads();
    }
}

__global__ void scatter_kernel(const int* __restrict__ row, const int* __restrict__ col) {
    int e = blockIdx.x * blockDim.x + threadIdx.x;
    if (e >= NEDGES) return;
    int r = row[e];
    int pos = atomicAdd(&g_cursor[r], 1);
    g_colp[pos] = col[e];
}

// ---------------- per-layer kernels ----------------
// repack W[h, d, o] -> B[d, h*HID+o]  (dense [D x Hout] row-major)
__global__ void repack_kernel(const float* __restrict__ W, int D, int Hout, int HIDp) {
    int idx = blockIdx.x * blockDim.x + threadIdx.x;
    if (idx >= D * Hout) return;
    int d = idx / Hout, c = idx % Hout;
    int h = c / HIDp, o = c % HIDp;
    g_B[idx] = W[((size_t)h * D + d) * HIDp + o];
}

// 1 / max(||x_n||, 1e-12), warp per node
__global__ void invn_kernel(const float* __restrict__ x, int D) {
    int n = (blockIdx.x * blockDim.x + threadIdx.x) >> 5;
    int lane = threadIdx.x & 31;
    if (n >= NNODES) return;
    const float4* xr = (const float4*)(x + (size_t)n * D);
    int nq = D >> 2;
    float s = 0.f;
    for (int j = lane; j < nq; j += 32) {
        float4 a = xr[j];
        s += a.x * a.x + a.y * a.y + a.z * a.z + a.w * a.w;
    }
    #pragma unroll
    for (int o = 16; o; o >>= 1) s += __shfl_xor_sync(0xffffffffu, s, o);
    if (lane == 0) g_invn[n] = 1.f / fmaxf(sqrtf(s), 1e-12f);
}

// Row-stationary sim, 2-edge software pipeline (R9 winner, unchanged).
__global__ void sim_row_kernel(const float* __restrict__ x, int D) {
    int n = (blockIdx.x * blockDim.x + threadIdx.x) >> 5;
    int lane = threadIdx.x & 31;
    if (n >= NNODES) return;
    const float4* xr = (const float4*)(x + (size_t)n * D);
    float4 r0 = xr[lane];
    float4 r1 = make_float4(0.f, 0.f, 0.f, 0.f);
    if (D == 256) r1 = xr[32 + lane];
    float invn_n = g_invn[n];
    int i0 = g_rowptr[n], i1 = g_rowptr[n + 1];

    int i = i0;
    for (; i + 2 <= i1; i += 2) {
        int ca = g_colp[i], cb = g_colp[i + 1];
        const float4* xa = (const float4*)(x + (size_t)ca * D);
        const float4* xb = (const float4*)(x + (size_t)cb * D);
        float4 a0 = xa[lane];
        float4 b0 = xb[lane];
        float sa = r0.x * a0.x + r0.y * a0.y + r0.z * a0.z + r0.w * a0.w;
        float sb = r0.x * b0.x + r0.y * b0.y + r0.z * b0.z + r0.w * b0.w;
        if (D == 256) {
            float4 a1 = xa[32 + lane];
            float4 b1 = xb[32 + lane];
            sa += r1.x * a1.x + r1.y * a1.y + r1.z * a1.z + r1.w * a1.w;
            sb += r1.x * b1.x + r1.y * b1.y + r1.z * b1.z + r1.w * b1.w;
        }
        #pragma unroll
        for (int o = 16; o; o >>= 1) {
            sa += __shfl_xor_sync(0xffffffffu, sa, o);
            sb += __shfl_xor_sync(0xffffffffu, sb, o);
        }
        if (lane == 0) {
            sa *= invn_n * g_invn[ca];
            sb *= invn_n * g_invn[cb];
            g_simp[i]     = (sa < 0.1f) ? 0.f : sa;
            g_simp[i + 1] = (sb < 0.1f) ? 0.f : sb;
        }
    }
    if (i < i1) {
        int c = g_colp[i];
        const float4* xc = (const float4*)(x + (size_t)c * D);
        float4 b0 = xc[lane];
        float s = r0.x * b0.x + r0.y * b0.y + r0.z * b0.z + r0.w * b0.w;
        if (D == 256) {
            float4 b1 = xc[32 + lane];
            s += r1.x * b1.x + r1.y * b1.y + r1.z * b1.z + r1.w * b1.w;
        }
        #pragma unroll
        for (int o = 16; o; o >>= 1) s += __shfl_xor_sync(0xffffffffu, s, o);
        if (lane == 0) {
            s *= invn_n * g_invn[c];
            g_simp[i] = (s < 0.1f) ? 0.f : s;
        }
    }
}

// rowsum / degree / self weight, warp per node
__global__ void rownorm_kernel() {
    int n = (blockIdx.x * blockDim.x + threadIdx.x) >> 5;
    int lane = threadIdx.x & 31;
    if (n >= NNODES) return;
    int s0 = g_rowptr[n], s1 = g_rowptr[n + 1];
    float sum = 0.f;
    int cnt = 0;
    for (int i = s0 + lane; i < s1; i += 32) {
        float v = g_simp[i];
        sum += v;                 // v >= 0 (thresholded cosine), so |v| == v
        cnt += (v != 0.f);
    }
    #pragma unroll
    for (int o = 16; o; o >>= 1) {
        sum += __shfl_xor_sync(0xffffffffu, sum, o);
        cnt += __shfl_xor_sync(0xffffffffu, cnt, o);
    }
    if (lane == 0) {
        g_invrs[n] = (sum > 0.f) ? 1.f / sum : 0.f;
        g_wself[n] = expf(1.f / ((float)cnt + 1.f));
    }
}

// ---------------- 3xTF32 tensor-core GEMM (fp32-accurate) ----------------
__device__ __forceinline__ unsigned f2tf32(float f) {
    unsigned r;
    asm("cvt.rna.tf32.f32 %0, %1;" : "=r"(r) : "f"(f));
    return r;
}

__device__ __forceinline__ void mma_tf32(float c[4], unsigned a0, unsigned a1,
                                         unsigned a2, unsigned a3,
                                         unsigned b0, unsigned b1) {
    asm volatile(
        "mma.sync.aligned.m16n8k8.row.col.f32.tf32.tf32.f32 "
        "{%0,%1,%2,%3}, {%4,%5,%6,%7}, {%8,%9}, {%0,%1,%2,%3};"
        : "+f"(c[0]), "+f"(c[1]), "+f"(c[2]), "+f"(c[3])
        : "r"(a0), "r"(a1), "r"(a2), "r"(a3), "r"(b0), "r"(b1));
}

// C[M, Nc] = A[M, K] * B[K, Nc], BM=128 BN=64 BK=16, 8 warps (warp tile 32x32).
// Register-staged double buffering: tile k+1 is prefetched into registers
// with independent LDGs while tile k is consumed from smem, so the global
// load latency overlaps the MMA phase instead of being exposed per K-iter.
__global__ void __launch_bounds__(256)
mma_gemm_kernel(const float* __restrict__ A, const float* __restrict__ Bw,
                float* __restrict__ C, int M, int K, int Nc) {
    __shared__ unsigned AsHi[128][20];
    __shared__ unsigned AsLo[128][20];
    __shared__ unsigned BsHi[16][68];
    __shared__ unsigned BsLo[16][68];

    int tid = threadIdx.x;
    int lane = tid & 31, w = tid >> 5;
    int wm = w & 3, wn = w >> 2;       // 4 warps in M, 2 in N
    int g = lane >> 2, t = lane & 3;
    int rb = blockIdx.y * 128, cb = blockIdx.x * 64;

    // A-tile fetch coords (2 float4 per thread), B-tile (1 float4 per thread)
    int fa_r[2], fa_kq[2];
    fa_r[0] = tid >> 2;  fa_kq[0] = tid & 3;
    fa_r[1] = (tid + 256) >> 2; fa_kq[1] = (tid + 256) & 3;
    int fb_r = tid >> 4, fb_nq = tid & 15;

    float acc[2][4][4];
    #pragma unroll
    for (int mi = 0; mi < 2; mi++)
        #pragma unroll
        for (int ni = 0; ni < 4; ni++)
            #pragma unroll
            for (int j = 0; j < 4; j++) acc[mi][ni][j] = 0.f;

    float4 pa[2], pb;

    // prefetch tile 0 into registers
    {
        #pragma unroll
        for (int u = 0; u < 2; u++) {
            int gr = rb + fa_r[u];
            pa[u] = make_float4(0.f, 0.f, 0.f, 0.f);
            if (gr < M) pa[u] = *(const float4*)&A[(size_t)gr * K + fa_kq[u] * 4];
        }
        pb = *(const float4*)&Bw[(size_t)fb_r * Nc + cb + fb_nq * 4];
    }

    int nk = K / 16;
    for (int kt = 0; kt < nk; kt++) {
        // store prefetched tile (converted to hi/lo) into smem
        #pragma unroll
        for (int u = 0; u < 2; u++) {
            float vv[4] = {pa[u].x, pa[u].y, pa[u].z, pa[u].w};
            #pragma unroll
            for (int j = 0; j < 4; j++) {
                unsigned hi = f2tf32(vv[j]);
                AsHi[fa_r[u]][fa_kq[u] * 4 + j] = hi;
                AsLo[fa_r[u]][fa_kq[u] * 4 + j] = f2tf32(vv[j] - __uint_as_float(hi));
            }
        }
        {
            float vv[4] = {pb.x, pb.y, pb.z, pb.w};
            #pragma unroll
            for (int j = 0; j < 4; j++) {
                unsigned hi = f2tf32(vv[j]);
                BsHi[fb_r][fb_nq * 4 + j] = hi;
                BsLo[fb_r][fb_nq * 4 + j] = f2tf32(vv[j] - __uint_as_float(hi));
            }
        }
        __syncthreads();

        // prefetch next tile into registers (overlaps the MMA phase below)
        if (kt + 1 < nk) {
            int k0n = (kt + 1) * 16;
            #pragma unroll
            for (int u = 0; u < 2; u++) {
                int gr = rb + fa_r[u];
                pa[u] = make_float4(0.f, 0.f, 0.f, 0.f);
                if (gr < M) pa[u] = *(const float4*)&A[(size_t)gr * K + k0n + fa_kq[u] * 4];
            }
            pb = *(const float4*)&Bw[(size_t)(k0n + fb_r) * Nc + cb + fb_nq * 4];
        }

        #pragma unroll
        for (int kk = 0; kk < 16; kk += 8) {
            unsigned ah[2][4], al[2][4], bh[4][2], bl[4][2];
            #pragma unroll
            for (int mi = 0; mi < 2; mi++) {
                int r0 = wm * 32 + mi * 16 + g;
                ah[mi][0] = AsHi[r0][kk + t];     ah[mi][1] = AsHi[r0 + 8][kk + t];
                ah[mi][2] = AsHi[r0][kk + t + 4]; ah[mi][3] = AsHi[r0 + 8][kk + t + 4];
                al[mi][0] = AsLo[r0][kk + t];     al[mi][1] = AsLo[r0 + 8][kk + t];
                al[mi][2] = AsLo[r0][kk + t + 4]; al[mi][3] = AsLo[r0 + 8][kk + t + 4];
            }
            #pragma unroll
            for (int ni = 0; ni < 4; ni++) {
                int c0 = wn * 32 + ni * 8 + g;
                bh[ni][0] = BsHi[kk + t][c0]; bh[ni][1] = BsHi[kk + t + 4][c0];
                bl[ni][0] = BsLo[kk + t][c0]; bl[ni][1] = BsLo[kk + t + 4][c0];
            }
            #pragma unroll
            for (int mi = 0; mi < 2; mi++)
                #pragma unroll
                for (int ni = 0; ni < 4; ni++) {
                    // 3xTF32: hi*hi + hi*lo + lo*hi ~= fp32 product
                    mma_tf32(acc[mi][ni], ah[mi][0], ah[mi][1], ah[mi][2], ah[mi][3],
                             bh[ni][0], bh[ni][1]);
                    mma_tf32(acc[mi][ni], ah[mi][0], ah[mi][1], ah[mi][2], ah[mi][3],
                             bl[ni][0], bl[ni][1]);
                    mma_tf32(acc[mi][ni], al[mi][0], al[mi][1], al[mi][2], al[mi][3],
                             bh[ni][0], bh[ni][1]);
                }
        }
        __syncthreads();
    }

    #pragma unroll
    for (int mi = 0; mi < 2; mi++) {
        int row = rb + wm * 32 + mi * 16 + g;
        #pragma unroll
        for (int ni = 0; ni < 4; ni++) {
            int colc = cb + wn * 32 + ni * 8 + 2 * t;
            if (row < M)
                *(float2*)&C[(size_t)row * Nc + colc] =
                    make_float2(acc[mi][ni][0], acc[mi][ni][1]);
            if (row + 8 < M)
                *(float2*)&C[(size_t)(row + 8) * Nc + colc] =
                    make_float2(acc[mi][ni][2], acc[mi][ni][3]);
        }
    }
}

// plain tiled SGEMM (kept for the tiny N=16 final projection)
template <int BM, int BN, int BK, int TM, int TN>
__global__ void __launch_bounds__(256)
sgemm_kernel(const float* __restrict__ A, const float* __restrict__ Bw,
             float* __restrict__ C, int M, int K, int Nc) {
    static_assert((BM / TM) * (BN / TN) == 256, "grid of 256 threads");
    __shared__ float As[BK][BM + 4];
    __shared__ float Bs[BK][BN];
    constexpr int TCOLS = BN / TN;
    int tid = threadIdx.x;
    int tr = tid / TCOLS, tc = tid % TCOLS;
    int rb = blockIdx.y * BM, cb = blockIdx.x * BN;
    float acc[TM][TN];
    #pragma unroll
    for (int i = 0; i < TM; i++)
        #pragma unroll
        for (int j = 0; j < TN; j++) acc[i][j] = 0.f;

    for (int k0 = 0; k0 < K; k0 += BK) {
        for (int idx = tid; idx < BM * BK; idx += 256) {
            int r = idx / BK, c = idx % BK;
            int gr = rb + r;
            As[c][r] = (gr < M) ? A[(size_t)gr * K + k0 + c] : 0.f;
        }
        for (int idx = tid; idx < BK * BN; idx += 256) {
            int r = idx / BN, c = idx % BN;
            Bs[r][c] = Bw[(size_t)(k0 + r) * Nc + cb + c];
        }
        __syncthreads();
        #pragma unroll
        for (int k = 0; k < BK; k++) {
            float a[TM], b[TN];
            #pragma unroll
            for (int i = 0; i < TM; i++) a[i] = As[k][tr * TM + i];
            #pragma unroll
            for (int j = 0; j < TN; j++) b[j] = Bs[k][tc * TN + j];
            #pragma unroll
            for (int i = 0; i < TM; i++)
                #pragma unroll
                for (int j = 0; j < TN; j++) acc[i][j] += a[i] * b[j];
        }
        __syncthreads();
    }
    #pragma unroll
    for (int i = 0; i < TM; i++) {
        int gr = rb + tr * TM + i;
        if (gr < M) {
            #pragma unroll
            for (int j = 0; j < TN; j++)
                C[(size_t)gr * Nc + cb + tc * TN + j] = acc[i][j];
        }
    }
}

// aggregation, Hout = 256: warp per node, lane owns 4+4 contiguous cols
__global__ void agg256_kernel(const float* __restrict__ z, float* __restrict__ out, int act) {
    int n = (blockIdx.x * blockDim.x + threadIdx.x) >> 5;
    int lane = threadIdx.x & 31;
    if (n >= NNODES) return;
    const float4* zr = (const float4*)(z + (size_t)n * 256);
    float ws = g_wself[n];
    float4 a0 = zr[lane], a1 = zr[32 + lane];
    a0.x *= ws; a0.y *= ws; a0.z *= ws; a0.w *= ws;
    a1.x *= ws; a1.y *= ws; a1.z *= ws; a1.w *= ws;
    float irs = g_invrs[n];
    int s1 = g_rowptr[n + 1];
    for (int i = g_rowptr[n]; i < s1; ++i) {
        float sv = g_simp[i];
        if (sv == 0.f) continue;
        float w = expf(sv * irs);
        const float4* zc = (const float4*)(z + (size_t)g_colp[i] * 256);
        float4 b0 = zc[lane], b1 = zc[32 + lane];
        a0.x += w * b0.x; a0.y += w * b0.y; a0.z += w * b0.z; a0.w += w * b0.w;
        a1.x += w * b1.x; a1.y += w * b1.y; a1.z += w * b1.z; a1.w += w * b1.w;
    }
    if (act) {
        a0.x = a0.x > 0.f ? a0.x : 0.01f * a0.x;
        a0.y = a0.y > 0.f ? a0.y : 0.01f * a0.y;
        a0.z = a0.z > 0.f ? a0.z : 0.01f * a0.z;
        a0.w = a0.w > 0.f ? a0.w : 0.01f * a0.w;
        a1.x = a1.x > 0.f ? a1.x : 0.01f * a1.x;
        a1.y = a1.y > 0.f ? a1.y : 0.01f * a1.y;
        a1.z = a1.z > 0.f ? a1.z : 0.01f * a1.z;
        a1.w = a1.w > 0.f ? a1.w : 0.01f * a1.w;
    }
    float4* o = (float4*)(out + (size_t)n * 256);
    o[lane] = a0; o[32 + lane] = a1;
}

// aggregation, Hout = 16 (final layer, no activation)
__global__ void agg16_kernel(const float* __restrict__ z, float* __restrict__ out) {
    int n = (blockIdx.x * blockDim.x + threadIdx.x) >> 5;
    int lane = threadIdx.x & 31;
    if (n >= NNODES || lane >= 16) return;
    float acc = g_wself[n] * z[(size_t)n * 16 + lane];
    float irs = g_invrs[n];
    int s1 = g_rowptr[n + 1];
    for (int i = g_rowptr[n]; i < s1; ++i) {
        float sv = g_simp[i];
        if (sv == 0.f) continue;
        acc += expf(sv * irs) * z[(size_t)g_colp[i] * 16 + lane];
    }
    out[(size_t)n * 16 + lane] = acc;
}

// ---------------- host side ----------------
static void run_layer(const float* xin, int D, const float* W, int HIDp, int Hout,
                      float* outp, bool act, float* zp) {
    repack_kernel<<<(D * Hout + 255) / 256, 256>>>(W, D, Hout, HIDp);
    invn_kernel<<<(NNODES + 7) / 8, 256>>>(xin, D);
    sim_row_kernel<<<(NNODES + 7) / 8, 256>>>(xin, D);
    rownorm_kernel<<<(NNODES + 7) / 8, 256>>>();
    float* Bdev;
    cudaGetSymbolAddress((void**)&Bdev, g_B);
    if (Hout == 256) {
        dim3 grid(256 / 64, (NNODES + 127) / 128);
        mma_gemm_kernel<<<grid, 256>>>(xin, Bdev, zp, NNODES, D, 256);
        agg256_kernel<<<(NNODES + 7) / 8, 256>>>(zp, outp, act ? 1 : 0);
    } else {
        dim3 grid(1, (NNODES + 63) / 64);
        sgemm_kernel<64, 16, 16, 4, 1><<<grid, 256>>>(xin, Bdev, zp, NNODES, D, 16);
        agg16_kernel<<<(NNODES + 7) / 8, 256>>>(zp, outp);
    }
}

extern "C" void kernel_launch(void* const* d_in, const int* in_sizes, int n_in,
                              void* d_out, int out_size) {
    const float* x  = (const float*)d_in[0];
    const float* W0 = (const float*)d_in[1];
    const float* W1 = (const float*)d_in[2];
    const float* W2 = (const float*)d_in[3];
    const int*   row = (const int*)d_in[4];
    const int*   col = (const int*)d_in[5];
    float* out = (float*)d_out;

    float *zp, *h1p, *h2p;
    cudaGetSymbolAddress((void**)&zp,  g_z);
    cudaGetSymbolAddress((void**)&h1p, g_h1);
    cudaGetSymbolAddress((void**)&h2p, g_h2);

    // CSR build (recomputed every call; deterministic work)
    zero_cnt_kernel<<<(NNODES + 255) / 256, 256>>>();
    hist_kernel<<<(NEDGES + 255) / 256, 256>>>(row);
    scan_kernel<<<1, 1024>>>();
    scatter_kernel<<<(NEDGES + 255) / 256, 256>>>(row, col);

    // layer 0: D=128, W0[4,128,64] -> h1[N,256], leaky relu
    run_layer(x,   128, W0, 64, 256, h1p, true,  zp);
    // layer 1: D=256, W1[4,256,64] -> h2[N,256], leaky relu
    run_layer(h1p, 256, W1, 64, 256, h2p, true,  zp);
    // layer 2: D=256, W2[1,256,16] -> out[N,16], no activation
    run_layer(h2p, 256, W2, 16, 16,  out, false, zp);
}

// round 11
// speedup vs baseline: 1.4896x; 1.4896x over previous
#include <cuda_runtime.h>
#include <math.h>

#define NNODES 50000
#define NEDGES 800000

// ---------------- scratch (device globals: allocation-free) ----------------
__device__ int   g_cnt[NNODES];
__device__ int   g_cursor[NNODES];
__device__ int   g_rowptr[NNODES + 1];
__device__ int   g_colp[NEDGES];
__device__ float g_simp[NEDGES];
__device__ float g_invn[NNODES];
__device__ float g_invrs[NNODES];
__device__ float g_wself[NNODES];
__device__ float g_z [NNODES * 256];
__device__ float g_h1[NNODES * 256];
__device__ float g_h2[NNODES * 256];
__device__ float g_B [256 * 256];

// ---------------- CSR build ----------------
__global__ void zero_cnt_kernel() {
    int i = blockIdx.x * blockDim.x + threadIdx.x;
    if (i < NNODES) g_cnt[i] = 0;
}

__global__ void hist_kernel(const int* __restrict__ row) {
    int e = blockIdx.x * blockDim.x + threadIdx.x;
    if (e < NEDGES) atomicAdd(&g_cnt[row[e]], 1);
}

__global__ void scan_kernel() {
    __shared__ int wsum[32];
    __shared__ int carry;
    int tid = threadIdx.x, lane = tid & 31, wid = tid >> 5;
    if (tid == 0) { carry = 0; g_rowptr[0] = 0; }
    __syncthreads();
    for (int base = 0; base < NNODES; base += 1024) {
        int i = base + tid;
        int v = (i < NNODES) ? g_cnt[i] : 0;
        int s = v;
        #pragma unroll
        for (int o = 1; o < 32; o <<= 1) {
            int t = __shfl_up_sync(0xffffffffu, s, o);
            if (lane >= o) s += t;
        }
        if (lane == 31) wsum[wid] = s;
        __syncthreads();
        if (wid == 0) {
            int ws = wsum[lane];
            #pragma unroll
            for (int o = 1; o < 32; o <<= 1) {
                int t = __shfl_up_sync(0xffffffffu, ws, o);
                if (lane >= o) ws += t;
            }
            wsum[lane] = ws;
        }
        __syncthreads();
        int incl = s + (wid ? wsum[wid - 1] : 0) + carry;
        if (i < NNODES) { g_rowptr[i + 1] = incl; g_cursor[i] = incl - v; }
        __syncthreads();
        if (tid == 1023) carry = incl;
        __syncthreads();
    }
}

__global__ void scatter_kernel(const int* __restrict__ row, const int* __restrict__ col) {
    int e = blockIdx.x * blockDim.x + threadIdx.x;
    if (e >= NEDGES) return;
    int r = row[e];
    int pos = atomicAdd(&g_cursor[r], 1);
    g_colp[pos] = col[e];
}

// ---------------- per-layer kernels ----------------
// repack W[h, d, o] -> B[d, h*HID+o]  (dense [D x Hout] row-major)
__global__ void repack_kernel(const float* __restrict__ W, int D, int Hout, int HIDp) {
    int idx = blockIdx.x * blockDim.x + threadIdx.x;
    if (idx >= D * Hout) return;
    int d = idx / Hout, c = idx % Hout;
    int h = c / HIDp, o = c % HIDp;
    g_B[idx] = W[((size_t)h * D + d) * HIDp + o];
}

// 1 / max(||x_n||, 1e-12), warp per node
__global__ void invn_kernel(const float* __restrict__ x, int D) {
    int n = (blockIdx.x * blockDim.x + threadIdx.x) >> 5;
    int lane = threadIdx.x & 31;
    if (n >= NNODES) return;
    const float4* xr = (const float4*)(x + (size_t)n * D);
    int nq = D >> 2;
    float s = 0.f;
    for (int j = lane; j < nq; j += 32) {
        float4 a = xr[j];
        s += a.x * a.x + a.y * a.y + a.z * a.z + a.w * a.w;
    }
    #pragma unroll
    for (int o = 16; o; o >>= 1) s += __shfl_xor_sync(0xffffffffu, s, o);
    if (lane == 0) g_invn[n] = 1.f / fmaxf(sqrtf(s), 1e-12f);
}

// Row-stationary sim, 4-edge software pipeline: four independent col gathers
// and dot/reduction chains in flight per iteration (extends the proven 2-edge
// win). Per-edge load pattern and math order unchanged -> bit-identical simp.
__global__ void sim_row_kernel(const float* __restrict__ x, int D) {
    int n = (blockIdx.x * blockDim.x + threadIdx.x) >> 5;
    int lane = threadIdx.x & 31;
    if (n >= NNODES) return;
    const float4* xr = (const float4*)(x + (size_t)n * D);
    float4 r0 = xr[lane];
    float4 r1 = make_float4(0.f, 0.f, 0.f, 0.f);
    if (D == 256) r1 = xr[32 + lane];
    float invn_n = g_invn[n];
    int i0 = g_rowptr[n], i1 = g_rowptr[n + 1];

    int i = i0;
    for (; i + 4 <= i1; i += 4) {
        int c0 = g_colp[i], c1 = g_colp[i + 1], c2 = g_colp[i + 2], c3 = g_colp[i + 3];
        const float4* x0 = (const float4*)(x + (size_t)c0 * D);
        const float4* x1 = (const float4*)(x + (size_t)c1 * D);
        const float4* x2 = (const float4*)(x + (size_t)c2 * D);
        const float4* x3 = (const float4*)(x + (size_t)c3 * D);
        float4 a0 = x0[lane], b0 = x1[lane], d0 = x2[lane], e0 = x3[lane];
        float s0 = r0.x * a0.x + r0.y * a0.y + r0.z * a0.z + r0.w * a0.w;
        float s1 = r0.x * b0.x + r0.y * b0.y + r0.z * b0.z + r0.w * b0.w;
        float s2 = r0.x * d0.x + r0.y * d0.y + r0.z * d0.z + r0.w * d0.w;
        float s3 = r0.x * e0.x + r0.y * e0.y + r0.z * e0.z + r0.w * e0.w;
        if (D == 256) {
            float4 a1 = x0[32 + lane], b1 = x1[32 + lane];
            float4 d1 = x2[32 + lane], e1 = x3[32 + lane];
            s0 += r1.x * a1.x + r1.y * a1.y + r1.z * a1.z + r1.w * a1.w;
            s1 += r1.x * b1.x + r1.y * b1.y + r1.z * b1.z + r1.w * b1.w;
            s2 += r1.x * d1.x + r1.y * d1.y + r1.z * d1.z + r1.w * d1.w;
            s3 += r1.x * e1.x + r1.y * e1.y + r1.z * e1.z + r1.w * e1.w;
        }
        #pragma unroll
        for (int o = 16; o; o >>= 1) {
            s0 += __shfl_xor_sync(0xffffffffu, s0, o);
            s1 += __shfl_xor_sync(0xffffffffu, s1, o);
            s2 += __shfl_xor_sync(0xffffffffu, s2, o);
            s3 += __shfl_xor_sync(0xffffffffu, s3, o);
        }
        if (lane == 0) {
            s0 *= invn_n * g_invn[c0];
            s1 *= invn_n * g_invn[c1];
            s2 *= invn_n * g_invn[c2];
            s3 *= invn_n * g_invn[c3];
            g_simp[i]     = (s0 < 0.1f) ? 0.f : s0;
            g_simp[i + 1] = (s1 < 0.1f) ? 0.f : s1;
            g_simp[i + 2] = (s2 < 0.1f) ? 0.f : s2;
            g_simp[i + 3] = (s3 < 0.1f) ? 0.f : s3;
        }
    }
    for (; i < i1; ++i) {
        int c = g_colp[i];
        const float4* xc = (const float4*)(x + (size_t)c * D);
        float4 b0 = xc[lane];
        float s = r0.x * b0.x + r0.y * b0.y + r0.z * b0.z + r0.w * b0.w;
        if (D == 256) {
            float4 b1 = xc[32 + lane];
            s += r1.x * b1.x + r1.y * b1.y + r1.z * b1.z + r1.w * b1.w;
        }
        #pragma unroll
        for (int o = 16; o; o >>= 1) s += __shfl_xor_sync(0xffffffffu, s, o);
        if (lane == 0) {
            s *= invn_n * g_invn[c];
            g_simp[i] = (s < 0.1f) ? 0.f : s;
        }
    }
}

// rowsum / degree / self weight, warp per node
__global__ void rownorm_kernel() {
    int n = (blockIdx.x * blockDim.x + threadIdx.x) >> 5;
    int lane = threadIdx.x & 31;
    if (n >= NNODES) return;
    int s0 = g_rowptr[n], s1 = g_rowptr[n + 1];
    float sum = 0.f;
    int cnt = 0;
    for (int i = s0 + lane; i < s1; i += 32) {
        float v = g_simp[i];
        sum += v;                 // v >= 0 (thresholded cosine), so |v| == v
        cnt += (v != 0.f);
    }
    #pragma unroll
    for (int o = 16; o; o >>= 1) {
        sum += __shfl_xor_sync(0xffffffffu, sum, o);
        cnt += __shfl_xor_sync(0xffffffffu, cnt, o);
    }
    if (lane == 0) {
        g_invrs[n] = (sum > 0.f) ? 1.f / sum : 0.f;
        g_wself[n] = expf(1.f / ((float)cnt + 1.f));
    }
}

// ---------------- 3xTF32 tensor-core GEMM (fp32-accurate) ----------------
__device__ __forceinline__ unsigned f2tf32(float f) {
    unsigned r;
    asm("cvt.rna.tf32.f32 %0, %1;" : "=r"(r) : "f"(f));
    return r;
}

__device__ __forceinline__ void mma_tf32(float c[4], unsigned a0, unsigned a1,
                                         unsigned a2, unsigned a3,
                                         unsigned b0, unsigned b1) {
    asm volatile(
        "mma.sync.aligned.m16n8k8.row.col.f32.tf32.tf32.f32 "
        "{%0,%1,%2,%3}, {%4,%5,%6,%7}, {%8,%9}, {%0,%1,%2,%3};"
        : "+f"(c[0]), "+f"(c[1]), "+f"(c[2]), "+f"(c[3])
        : "r"(a0), "r"(a1), "r"(a2), "r"(a3), "r"(b0), "r"(b1));
}

// C[M, Nc] = A[M, K] * B[K, Nc], BM=128 BN=64 BK=16, 8 warps (warp tile 32x32)
// (R9 serial schedule — the double-buffered variant hit a register cliff.)
__global__ void __launch_bounds__(256)
mma_gemm_kernel(const float* __restrict__ A, const float* __restrict__ Bw,
                float* __restrict__ C, int M, int K, int Nc) {
    __shared__ unsigned AsHi[128][20];
    __shared__ unsigned AsLo[128][20];
    __shared__ unsigned BsHi[16][68];
    __shared__ unsigned BsLo[16][68];

    int tid = threadIdx.x;
    int lane = tid & 31, w = tid >> 5;
    int wm = w & 3, wn = w >> 2;       // 4 warps in M, 2 in N
    int g = lane >> 2, t = lane & 3;
    int rb = blockIdx.y * 128, cb = blockIdx.x * 64;

    float acc[2][4][4];
    #pragma unroll
    for (int mi = 0; mi < 2; mi++)
        #pragma unroll
        for (int ni = 0; ni < 4; ni++)
            #pragma unroll
            for (int j = 0; j < 4; j++) acc[mi][ni][j] = 0.f;

    for (int k0 = 0; k0 < K; k0 += 16) {
        // A tile 128x16 -> 512 float4, 2 per thread
        #pragma unroll
        for (int f = tid; f < 512; f += 256) {
            int r = f >> 2, kq = f & 3;
            int gr = rb + r;
            float4 v = make_float4(0.f, 0.f, 0.f, 0.f);
            if (gr < M) v = *(const float4*)&A[(size_t)gr * K + k0 + kq * 4];
            float vv[4] = {v.x, v.y, v.z, v.w};
            #pragma unroll
            for (int j = 0; j < 4; j++) {
                unsigned hi = f2tf32(vv[j]);
                AsHi[r][kq * 4 + j] = hi;
                AsLo[r][kq * 4 + j] = f2tf32(vv[j] - __uint_as_float(hi));
            }
        }
        // B tile 16x64 -> 256 float4, 1 per thread
        {
            int r = tid >> 4, nq = tid & 15;
            float4 v = *(const float4*)&Bw[(size_t)(k0 + r) * Nc + cb + nq * 4];
            float vv[4] = {v.x, v.y, v.z, v.w};
            #pragma unroll
            for (int j = 0; j < 4; j++) {
                unsigned hi = f2tf32(vv[j]);
                BsHi[r][nq * 4 + j] = hi;
                BsLo[r][nq * 4 + j] = f2tf32(vv[j] - __uint_as_float(hi));
            }
        }
        __syncthreads();

        #pragma unroll
        for (int kk = 0; kk < 16; kk += 8) {
            unsigned ah[2][4], al[2][4], bh[4][2], bl[4][2];
            #pragma unroll
            for (int mi = 0; mi < 2; mi++) {
                int r0 = wm * 32 + mi * 16 + g;
                ah[mi][0] = AsHi[r0][kk + t];     ah[mi][1] = AsHi[r0 + 8][kk + t];
                ah[mi][2] = AsHi[r0][kk + t + 4]; ah[mi][3] = AsHi[r0 + 8][kk + t + 4];
                al[mi][0] = AsLo[r0][kk + t];     al[mi][1] = AsLo[r0 + 8][kk + t];
                al[mi][2] = AsLo[r0][kk + t + 4]; al[mi][3] = AsLo[r0 + 8][kk + t + 4];
            }
            #pragma unroll
            for (int ni = 0; ni < 4; ni++) {
                int c0 = wn * 32 + ni * 8 + g;
                bh[ni][0] = BsHi[kk + t][c0]; bh[ni][1] = BsHi[kk + t + 4][c0];
                bl[ni][0] = BsLo[kk + t][c0]; bl[ni][1] = BsLo[kk + t + 4][c0];
            }
            #pragma unroll
            for (int mi = 0; mi < 2; mi++)
                #pragma unroll
                for (int ni = 0; ni < 4; ni++) {
                    // 3xTF32: hi*hi + hi*lo + lo*hi ~= fp32 product
                    mma_tf32(acc[mi][ni], ah[mi][0], ah[mi][1], ah[mi][2], ah[mi][3],
                             bh[ni][0], bh[ni][1]);
                    mma_tf32(acc[mi][ni], ah[mi][0], ah[mi][1], ah[mi][2], ah[mi][3],
                             bl[ni][0], bl[ni][1]);
                    mma_tf32(acc[mi][ni], al[mi][0], al[mi][1], al[mi][2], al[mi][3],
                             bh[ni][0], bh[ni][1]);
                }
        }
        __syncthreads();
    }

    #pragma unroll
    for (int mi = 0; mi < 2; mi++) {
        int row = rb + wm * 32 + mi * 16 + g;
        #pragma unroll
        for (int ni = 0; ni < 4; ni++) {
            int colc = cb + wn * 32 + ni * 8 + 2 * t;
            if (row < M)
                *(float2*)&C[(size_t)row * Nc + colc] =
                    make_float2(acc[mi][ni][0], acc[mi][ni][1]);
            if (row + 8 < M)
                *(float2*)&C[(size_t)(row + 8) * Nc + colc] =
                    make_float2(acc[mi][ni][2], acc[mi][ni][3]);
        }
    }
}

// plain tiled SGEMM (kept for the tiny N=16 final projection)
template <int BM, int BN, int BK, int TM, int TN>
__global__ void __launch_bounds__(256)
sgemm_kernel(const float* __restrict__ A, const float* __restrict__ Bw,
             float* __restrict__ C, int M, int K, int Nc) {
    static_assert((BM / TM) * (BN / TN) == 256, "grid of 256 threads");
    __shared__ float As[BK][BM + 4];
    __shared__ float Bs[BK][BN];
    constexpr int TCOLS = BN / TN;
    int tid = threadIdx.x;
    int tr = tid / TCOLS, tc = tid % TCOLS;
    int rb = blockIdx.y * BM, cb = blockIdx.x * BN;
    float acc[TM][TN];
    #pragma unroll
    for (int i = 0; i < TM; i++)
        #pragma unroll
        for (int j = 0; j < TN; j++) acc[i][j] = 0.f;

    for (int k0 = 0; k0 < K; k0 += BK) {
        for (int idx = tid; idx < BM * BK; idx += 256) {
            int r = idx / BK, c = idx % BK;
            int gr = rb + r;
            As[c][r] = (gr < M) ? A[(size_t)gr * K + k0 + c] : 0.f;
        }
        for (int idx = tid; idx < BK * BN; idx += 256) {
            int r = idx / BN, c = idx % BN;
            Bs[r][c] = Bw[(size_t)(k0 + r) * Nc + cb + c];
        }
        __syncthreads();
        #pragma unroll
        for (int k = 0; k < BK; k++) {
            float a[TM], b[TN];
            #pragma unroll
            for (int i = 0; i < TM; i++) a[i] = As[k][tr * TM + i];
            #pragma unroll
            for (int j = 0; j < TN; j++) b[j] = Bs[k][tc * TN + j];
            #pragma unroll
            for (int i = 0; i < TM; i++)
                #pragma unroll
                for (int j = 0; j < TN; j++) acc[i][j] += a[i] * b[j];
        }
        __syncthreads();
    }
    #pragma unroll
    for (int i = 0; i < TM; i++) {
        int gr = rb + tr * TM + i;
        if (gr < M) {
            #pragma unroll
            for (int j = 0; j < TN; j++)
                C[(size_t)gr * Nc + cb + tc * TN + j] = acc[i][j];
        }
    }
}

// aggregation, Hout = 256: warp per node, lane owns 4+4 contiguous cols
__global__ void agg256_kernel(const float* __restrict__ z, float* __restrict__ out, int act) {
    int n = (blockIdx.x * blockDim.x + threadIdx.x) >> 5;
    int lane = threadIdx.x & 31;
    if (n >= NNODES) return;
    const float4* zr = (const float4*)(z + (size_t)n * 256);
    float ws = g_wself[n];
    float4 a0 = zr[lane], a1 = zr[32 + lane];
    a0.x *= ws; a0.y *= ws; a0.z *= ws; a0.w *= ws;
    a1.x *= ws; a1.y *= ws; a1.z *= ws; a1.w *= ws;
    float irs = g_invrs[n];
    int s1 = g_rowptr[n + 1];
    for (int i = g_rowptr[n]; i < s1; ++i) {
        float sv = g_simp[i];
        if (sv == 0.f) continue;
        float w = expf(sv * irs);
        const float4* zc = (const float4*)(z + (size_t)g_colp[i] * 256);
        float4 b0 = zc[lane], b1 = zc[32 + lane];
        a0.x += w * b0.x; a0.y += w * b0.y; a0.z += w * b0.z; a0.w += w * b0.w;
        a1.x += w * b1.x; a1.y += w * b1.y; a1.z += w * b1.z; a1.w += w * b1.w;
    }
    if (act) {
        a0.x = a0.x > 0.f ? a0.x : 0.01f * a0.x;
        a0.y = a0.y > 0.f ? a0.y : 0.01f * a0.y;
        a0.z = a0.z > 0.f ? a0.z : 0.01f * a0.z;
        a0.w = a0.w > 0.f ? a0.w : 0.01f * a0.w;
        a1.x = a1.x > 0.f ? a1.x : 0.01f * a1.x;
        a1.y = a1.y > 0.f ? a1.y : 0.01f * a1.y;
        a1.z = a1.z > 0.f ? a1.z : 0.01f * a1.z;
        a1.w = a1.w > 0.f ? a1.w : 0.01f * a1.w;
    }
    float4* o = (float4*)(out + (size_t)n * 256);
    o[lane] = a0; o[32 + lane] = a1;
}

// aggregation, Hout = 16 (final layer, no activation)
__global__ void agg16_kernel(const float* __restrict__ z, float* __restrict__ out) {
    int n = (blockIdx.x * blockDim.x + threadIdx.x) >> 5;
    int lane = threadIdx.x & 31;
    if (n >= NNODES || lane >= 16) return;
    float acc = g_wself[n] * z[(size_t)n * 16 + lane];
    float irs = g_invrs[n];
    int s1 = g_rowptr[n + 1];
    for (int i = g_rowptr[n]; i < s1; ++i) {
        float sv = g_simp[i];
        if (sv == 0.f) continue;
        acc += expf(sv * irs) * z[(size_t)g_colp[i] * 16 + lane];
    }
    out[(size_t)n * 16 + lane] = acc;
}

// ---------------- host side ----------------
static void run_layer(const float* xin, int D, const float* W, int HIDp, int Hout,
                      float* outp, bool act, float* zp) {
    repack_kernel<<<(D * Hout + 255) / 256, 256>>>(W, D, Hout, HIDp);
    invn_kernel<<<(NNODES + 7) / 8, 256>>>(xin, D);
    sim_row_kernel<<<(NNODES + 7) / 8, 256>>>(xin, D);
    rownorm_kernel<<<(NNODES + 7) / 8, 256>>>();
    float* Bdev;
    cudaGetSymbolAddress((void**)&Bdev, g_B);
    if (Hout == 256) {
        dim3 grid(256 / 64, (NNODES + 127) / 128);
        mma_gemm_kernel<<<grid, 256>>>(xin, Bdev, zp, NNODES, D, 256);
        agg256_kernel<<<(NNODES + 7) / 8, 256>>>(zp, outp, act ? 1 : 0);
    } else {
        dim3 grid(1, (NNODES + 63) / 64);
        sgemm_kernel<64, 16, 16, 4, 1><<<grid, 256>>>(xin, Bdev, zp, NNODES, D, 16);
        agg16_kernel<<<(NNODES + 7) / 8, 256>>>(zp, outp);
    }
}

extern "C" void kernel_launch(void* const* d_in, const int* in_sizes, int n_in,
                              void* d_out, int out_size) {
    const float* x  = (const float*)d_in[0];
    const float* W0 = (const float*)d_in[1];
    const float* W1 = (const float*)d_in[2];
    const float* W2 = (const float*)d_in[3];
    const int*   row = (const int*)d_in[4];
    const int*   col = (const int*)d_in[5];
    float* out = (float*)d_out;

    float *zp, *h1p, *h2p;
    cudaGetSymbolAddress((void**)&zp,  g_z);
    cudaGetSymbolAddress((void**)&h1p, g_h1);
    cudaGetSymbolAddress((void**)&h2p, g_h2);

    // CSR build (recomputed every call; deterministic work)
    zero_cnt_kernel<<<(NNODES + 255) / 256, 256>>>();
    hist_kernel<<<(NEDGES + 255) / 256, 256>>>(row);
    scan_kernel<<<1, 1024>>>();
    scatter_kernel<<<(NEDGES + 255) / 256, 256>>>(row, col);

    // layer 0: D=128, W0[4,128,64] -> h1[N,256], leaky relu
    run_layer(x,   128, W0, 64, 256, h1p, true,  zp);
    // layer 1: D=256, W1[4,256,64] -> h2[N,256], leaky relu
    run_layer(h1p, 256, W1, 64, 256, h2p, true,  zp);
    // layer 2: D=256, W2[1,256,16] -> out[N,16], no activation
    run_layer(h2p, 256, W2, 16, 16,  out, false, zp);
}

// round 12
// speedup vs baseline: 1.5106x; 1.0141x over previous
#include <cuda_runtime.h>
#include <math.h>

#define NNODES 50000
#define NEDGES 800000

// ---------------- scratch (device globals: allocation-free) ----------------
__device__ int   g_cnt[NNODES];
__device__ int   g_cursor[NNODES];
__device__ int   g_rowptr[NNODES + 1];
__device__ int   g_colp[NEDGES];
__device__ float g_simp[NEDGES];
__device__ float g_invn[NNODES];
__device__ float g_invrs[NNODES];
__device__ float g_wself[NNODES];
__device__ float g_z [NNODES * 256];
__device__ float g_h1[NNODES * 256];
__device__ float g_h2[NNODES * 256];
__device__ float g_B [256 * 256];

// ---------------- CSR build ----------------
__global__ void zero_cnt_kernel() {
    int i = blockIdx.x * blockDim.x + threadIdx.x;
    if (i < NNODES) g_cnt[i] = 0;
}

__global__ void hist_kernel(const int* __restrict__ row) {
    int e = blockIdx.x * blockDim.x + threadIdx.x;
    if (e < NEDGES) atomicAdd(&g_cnt[row[e]], 1);
}

__global__ void scan_kernel() {
    __shared__ int wsum[32];
    __shared__ int carry;
    int tid = threadIdx.x, lane = tid & 31, wid = tid >> 5;
    if (tid == 0) { carry = 0; g_rowptr[0] = 0; }
    __syncthreads();
    for (int base = 0; base < NNODES; base += 1024) {
        int i = base + tid;
        int v = (i < NNODES) ? g_cnt[i] : 0;
        int s = v;
        #pragma unroll
        for (int o = 1; o < 32; o <<= 1) {
            int t = __shfl_up_sync(0xffffffffu, s, o);
            if (lane >= o) s += t;
        }
        if (lane == 31) wsum[wid] = s;
        __syncthreads();
        if (wid == 0) {
            int ws = wsum[lane];
            #pragma unroll
            for (int o = 1; o < 32; o <<= 1) {
                int t = __shfl_up_sync(0xffffffffu, ws, o);
                if (lane >= o) ws += t;
            }
            wsum[lane] = ws;
        }
        __syncthreads();
        int incl = s + (wid ? wsum[wid - 1] : 0) + carry;
        if (i < NNODES) { g_rowptr[i + 1] = incl; g_cursor[i] = incl - v; }
        __syncthreads();
        if (tid == 1023) carry = incl;
        __syncthreads();
    }
}

__global__ void scatter_kernel(const int* __restrict__ row, const int* __restrict__ col) {
    int e = blockIdx.x * blockDim.x + threadIdx.x;
    if (e >= NEDGES) return;
    int r = row[e];
    int pos = atomicAdd(&g_cursor[r], 1);
    g_colp[pos] = col[e];
}

// ---------------- per-layer kernels ----------------
// repack W[h, d, o] -> B[d, h*HID+o]  (dense [D x Hout] row-major)
__global__ void repack_kernel(const float* __restrict__ W, int D, int Hout, int HIDp) {
    int idx = blockIdx.x * blockDim.x + threadIdx.x;
    if (idx >= D * Hout) return;
    int d = idx / Hout, c = idx % Hout;
    int h = c / HIDp, o = c % HIDp;
    g_B[idx] = W[((size_t)h * D + d) * HIDp + o];
}

// 1 / max(||x_n||, 1e-12), warp per node
__global__ void invn_kernel(const float* __restrict__ x, int D) {
    int n = (blockIdx.x * blockDim.x + threadIdx.x) >> 5;
    int lane = threadIdx.x & 31;
    if (n >= NNODES) return;
    const float4* xr = (const float4*)(x + (size_t)n * D);
    int nq = D >> 2;
    float s = 0.f;
    for (int j = lane; j < nq; j += 32) {
        float4 a = xr[j];
        s += a.x * a.x + a.y * a.y + a.z * a.z + a.w * a.w;
    }
    #pragma unroll
    for (int o = 16; o; o >>= 1) s += __shfl_xor_sync(0xffffffffu, s, o);
    if (lane == 0) g_invn[n] = 1.f / fmaxf(sqrtf(s), 1e-12f);
}

// Row-stationary sim, 2-edge software pipeline (R9 winner, unchanged).
__global__ void sim_row_kernel(const float* __restrict__ x, int D) {
    int n = (blockIdx.x * blockDim.x + threadIdx.x) >> 5;
    int lane = threadIdx.x & 31;
    if (n >= NNODES) return;
    const float4* xr = (const float4*)(x + (size_t)n * D);
    float4 r0 = xr[lane];
    float4 r1 = make_float4(0.f, 0.f, 0.f, 0.f);
    if (D == 256) r1 = xr[32 + lane];
    float invn_n = g_invn[n];
    int i0 = g_rowptr[n], i1 = g_rowptr[n + 1];

    int i = i0;
    for (; i + 2 <= i1; i += 2) {
        int ca = g_colp[i], cb = g_colp[i + 1];
        const float4* xa = (const float4*)(x + (size_t)ca * D);
        const float4* xb = (const float4*)(x + (size_t)cb * D);
        float4 a0 = xa[lane];
        float4 b0 = xb[lane];
        float sa = r0.x * a0.x + r0.y * a0.y + r0.z * a0.z + r0.w * a0.w;
        float sb = r0.x * b0.x + r0.y * b0.y + r0.z * b0.z + r0.w * b0.w;
        if (D == 256) {
            float4 a1 = xa[32 + lane];
            float4 b1 = xb[32 + lane];
            sa += r1.x * a1.x + r1.y * a1.y + r1.z * a1.z + r1.w * a1.w;
            sb += r1.x * b1.x + r1.y * b1.y + r1.z * b1.z + r1.w * b1.w;
        }
        #pragma unroll
        for (int o = 16; o; o >>= 1) {
            sa += __shfl_xor_sync(0xffffffffu, sa, o);
            sb += __shfl_xor_sync(0xffffffffu, sb, o);
        }
        if (lane == 0) {
            sa *= invn_n * g_invn[ca];
            sb *= invn_n * g_invn[cb];
            g_simp[i]     = (sa < 0.1f) ? 0.f : sa;
            g_simp[i + 1] = (sb < 0.1f) ? 0.f : sb;
        }
    }
    if (i < i1) {
        int c = g_colp[i];
        const float4* xc = (const float4*)(x + (size_t)c * D);
        float4 b0 = xc[lane];
        float s = r0.x * b0.x + r0.y * b0.y + r0.z * b0.z + r0.w * b0.w;
        if (D == 256) {
            float4 b1 = xc[32 + lane];
            s += r1.x * b1.x + r1.y * b1.y + r1.z * b1.z + r1.w * b1.w;
        }
        #pragma unroll
        for (int o = 16; o; o >>= 1) s += __shfl_xor_sync(0xffffffffu, s, o);
        if (lane == 0) {
            s *= invn_n * g_invn[c];
            g_simp[i] = (s < 0.1f) ? 0.f : s;
        }
    }
}

// rowsum / degree / self weight, warp per node
__global__ void rownorm_kernel() {
    int n = (blockIdx.x * blockDim.x + threadIdx.x) >> 5;
    int lane = threadIdx.x & 31;
    if (n >= NNODES) return;
    int s0 = g_rowptr[n], s1 = g_rowptr[n + 1];
    float sum = 0.f;
    int cnt = 0;
    for (int i = s0 + lane; i < s1; i += 32) {
        float v = g_simp[i];
        sum += v;                 // v >= 0 (thresholded cosine), so |v| == v
        cnt += (v != 0.f);
    }
    #pragma unroll
    for (int o = 16; o; o >>= 1) {
        sum += __shfl_xor_sync(0xffffffffu, sum, o);
        cnt += __shfl_xor_sync(0xffffffffu, cnt, o);
    }
    if (lane == 0) {
        g_invrs[n] = (sum > 0.f) ? 1.f / sum : 0.f;
        g_wself[n] = expf(1.f / ((float)cnt + 1.f));
    }
}

// ---------------- 3xTF32 tensor-core GEMM (fp32-accurate) ----------------
__device__ __forceinline__ unsigned f2tf32(float f) {
    unsigned r;
    asm("cvt.rna.tf32.f32 %0, %1;" : "=r"(r) : "f"(f));
    return r;
}

__device__ __forceinline__ void mma_tf32(float c[4], unsigned a0, unsigned a1,
                                         unsigned a2, unsigned a3,
                                         unsigned b0, unsigned b1) {
    asm volatile(
        "mma.sync.aligned.m16n8k8.row.col.f32.tf32.tf32.f32 "
        "{%0,%1,%2,%3}, {%4,%5,%6,%7}, {%8,%9}, {%0,%1,%2,%3};"
        : "+f"(c[0]), "+f"(c[1]), "+f"(c[2]), "+f"(c[3])
        : "r"(a0), "r"(a1), "r"(a2), "r"(a3), "r"(b0), "r"(b1));
}

// cp.async 16B global->shared (zfill when pred=false; address clamped by caller)
__device__ __forceinline__ void cp16(void* dst_smem, const void* src, bool pred) {
    unsigned daddr = (unsigned)__cvta_generic_to_shared(dst_smem);
    int sz = pred ? 16 : 0;
    asm volatile("cp.async.cg.shared.global [%0], [%1], 16, %2;"
                 :: "r"(daddr), "l"(src), "r"(sz));
}
__device__ __forceinline__ void cp_commit()  { asm volatile("cp.async.commit_group;" ::: "memory"); }
__device__ __forceinline__ void cp_wait1()   { asm volatile("cp.async.wait_group 1;" ::: "memory"); }
__device__ __forceinline__ void cp_wait0()   { asm volatile("cp.async.wait_group 0;" ::: "memory"); }

// C[M, Nc] = A[M, K] * B[K, Nc], BM=128 BN=64 BK=16, 8 warps (warp tile 32x32).
// cp.async smem double-buffering of RAW tiles: tile k+1 streams global->smem
// (no registers involved) while tile k is converted to hi/lo and consumed.
// Register pressure identical to the serial R9 schedule.
__global__ void __launch_bounds__(256)
mma_gemm_kernel(const float* __restrict__ A, const float* __restrict__ Bw,
                float* __restrict__ C, int M, int K, int Nc) {
    __shared__ unsigned AsHi[128][20];
    __shared__ unsigned AsLo[128][20];
    __shared__ unsigned BsHi[16][68];
    __shared__ unsigned BsLo[16][68];
    __shared__ float4 rawA[2][512];
    __shared__ float4 rawB[2][256];

    int tid = threadIdx.x;
    int lane = tid & 31, w = tid >> 5;
    int wm = w & 3, wn = w >> 2;       // 4 warps in M, 2 in N
    int g = lane >> 2, t = lane & 3;
    int rb = blockIdx.y * 128, cb = blockIdx.x * 64;

    float acc[2][4][4];
    #pragma unroll
    for (int mi = 0; mi < 2; mi++)
        #pragma unroll
        for (int ni = 0; ni < 4; ni++)
            #pragma unroll
            for (int j = 0; j < 4; j++) acc[mi][ni][j] = 0.f;

    // issue tile copy for K-offset k0 into buffer buf
    auto issue_tile = [&](int buf, int k0) {
        #pragma unroll
        for (int u = 0; u < 2; u++) {
            int f = tid + u * 256;
            int r = f >> 2, kq = f & 3;
            int gr = rb + r;
            bool ok = (gr < M);
            int gcl = ok ? gr : (M - 1);
            cp16(&rawA[buf][f], &A[(size_t)gcl * K + k0 + kq * 4], ok);
        }
        cp16(&rawB[buf][tid],
             &Bw[(size_t)(k0 + (tid >> 4)) * Nc + cb + (tid & 15) * 4], true);
    };

    int nk = K / 16;
    issue_tile(0, 0);
    cp_commit();

    for (int kt = 0; kt < nk; kt++) {
        int buf = kt & 1;
        if (kt + 1 < nk) {
            issue_tile((kt + 1) & 1, (kt + 1) * 16);
            cp_commit();
            cp_wait1();            // tile kt landed; kt+1 still in flight
        } else {
            cp_wait0();
        }
        __syncthreads();           // raw tile kt visible to all

        // convert raw tile kt -> hi/lo smem
        #pragma unroll
        for (int u = 0; u < 2; u++) {
            int f = tid + u * 256;
            int r = f >> 2, kq = f & 3;
            float4 v = rawA[buf][f];
            float vv[4] = {v.x, v.y, v.z, v.w};
            #pragma unroll
            for (int j = 0; j < 4; j++) {
                unsigned hi = f2tf32(vv[j]);
                AsHi[r][kq * 4 + j] = hi;
                AsLo[r][kq * 4 + j] = f2tf32(vv[j] - __uint_as_float(hi));
            }
        }
        {
            int r = tid >> 4, nq = tid & 15;
            float4 v = rawB[buf][tid];
            float vv[4] = {v.x, v.y, v.z, v.w};
            #pragma unroll
            for (int j = 0; j < 4; j++) {
                unsigned hi = f2tf32(vv[j]);
                BsHi[r][nq * 4 + j] = hi;
                BsLo[r][nq * 4 + j] = f2tf32(vv[j] - __uint_as_float(hi));
            }
        }
        __syncthreads();           // hi/lo ready

        #pragma unroll
        for (int kk = 0; kk < 16; kk += 8) {
            unsigned ah[2][4], al[2][4], bh[4][2], bl[4][2];
            #pragma unroll
            for (int mi = 0; mi < 2; mi++) {
                int r0 = wm * 32 + mi * 16 + g;
                ah[mi][0] = AsHi[r0][kk + t];     ah[mi][1] = AsHi[r0 + 8][kk + t];
                ah[mi][2] = AsHi[r0][kk + t + 4]; ah[mi][3] = AsHi[r0 + 8][kk + t + 4];
                al[mi][0] = AsLo[r0][kk + t];     al[mi][1] = AsLo[r0 + 8][kk + t];
                al[mi][2] = AsLo[r0][kk + t + 4]; al[mi][3] = AsLo[r0 + 8][kk + t + 4];
            }
            #pragma unroll
            for (int ni = 0; ni < 4; ni++) {
                int c0 = wn * 32 + ni * 8 + g;
                bh[ni][0] = BsHi[kk + t][c0]; bh[ni][1] = BsHi[kk + t + 4][c0];
                bl[ni][0] = BsLo[kk + t][c0]; bl[ni][1] = BsLo[kk + t + 4][c0];
            }
            #pragma unroll
            for (int mi = 0; mi < 2; mi++)
                #pragma unroll
                for (int ni = 0; ni < 4; ni++) {
                    // 3xTF32: hi*hi + hi*lo + lo*hi ~= fp32 product
                    mma_tf32(acc[mi][ni], ah[mi][0], ah[mi][1], ah[mi][2], ah[mi][3],
                             bh[ni][0], bh[ni][1]);
                    mma_tf32(acc[mi][ni], ah[mi][0], ah[mi][1], ah[mi][2], ah[mi][3],
                             bl[ni][0], bl[ni][1]);
                    mma_tf32(acc[mi][ni], al[mi][0], al[mi][1], al[mi][2], al[mi][3],
                             bh[ni][0], bh[ni][1]);
                }
        }
        __syncthreads();           // done with hi/lo before next convert
    }

    #pragma unroll
    for (int mi = 0; mi < 2; mi++) {
        int row = rb + wm * 32 + mi * 16 + g;
        #pragma unroll
        for (int ni = 0; ni < 4; ni++) {
            int colc = cb + wn * 32 + ni * 8 + 2 * t;
            if (row < M)
                *(float2*)&C[(size_t)row * Nc + colc] =
                    make_float2(acc[mi][ni][0], acc[mi][ni][1]);
            if (row + 8 < M)
                *(float2*)&C[(size_t)(row + 8) * Nc + colc] =
                    make_float2(acc[mi][ni][2], acc[mi][ni][3]);
        }
    }
}

// plain tiled SGEMM (kept for the tiny N=16 final projection)
template <int BM, int BN, int BK, int TM, int TN>
__global__ void __launch_bounds__(256)
sgemm_kernel(const float* __restrict__ A, const float* __restrict__ Bw,
             float* __restrict__ C, int M, int K, int Nc) {
    static_assert((BM / TM) * (BN / TN) == 256, "grid of 256 threads");
    __shared__ float As[BK][BM + 4];
    __shared__ float Bs[BK][BN];
    constexpr int TCOLS = BN / TN;
    int tid = threadIdx.x;
    int tr = tid / TCOLS, tc = tid % TCOLS;
    int rb = blockIdx.y * BM, cb = blockIdx.x * BN;
    float acc[TM][TN];
    #pragma unroll
    for (int i = 0; i < TM; i++)
        #pragma unroll
        for (int j = 0; j < TN; j++) acc[i][j] = 0.f;

    for (int k0 = 0; k0 < K; k0 += BK) {
        for (int idx = tid; idx < BM * BK; idx += 256) {
            int r = idx / BK, c = idx % BK;
            int gr = rb + r;
            As[c][r] = (gr < M) ? A[(size_t)gr * K + k0 + c] : 0.f;
        }
        for (int idx = tid; idx < BK * BN; idx += 256) {
            int r = idx / BN, c = idx % BN;
            Bs[r][c] = Bw[(size_t)(k0 + r) * Nc + cb + c];
        }
        __syncthreads();
        #pragma unroll
        for (int k = 0; k < BK; k++) {
            float a[TM], b[TN];
            #pragma unroll
            for (int i = 0; i < TM; i++) a[i] = As[k][tr * TM + i];
            #pragma unroll
            for (int j = 0; j < TN; j++) b[j] = Bs[k][tc * TN + j];
            #pragma unroll
            for (int i = 0; i < TM; i++)
                #pragma unroll
                for (int j = 0; j < TN; j++) acc[i][j] += a[i] * b[j];
        }
        __syncthreads();
    }
    #pragma unroll
    for (int i = 0; i < TM; i++) {
        int gr = rb + tr * TM + i;
        if (gr < M) {
            #pragma unroll
            for (int j = 0; j < TN; j++)
                C[(size_t)gr * Nc + cb + tc * TN + j] = acc[i][j];
        }
    }
}

// aggregation, Hout = 256: warp per node, lane owns 4+4 contiguous cols
__global__ void agg256_kernel(const float* __restrict__ z, float* __restrict__ out, int act) {
    int n = (blockIdx.x * blockDim.x + threadIdx.x) >> 5;
    int lane = threadIdx.x & 31;
    if (n >= NNODES) return;
    const float4* zr = (const float4*)(z + (size_t)n * 256);
    float ws = g_wself[n];
    float4 a0 = zr[lane], a1 = zr[32 + lane];
    a0.x *= ws; a0.y *= ws; a0.z *= ws; a0.w *= ws;
    a1.x *= ws; a1.y *= ws; a1.z *= ws; a1.w *= ws;
    float irs = g_invrs[n];
    int s1 = g_rowptr[n + 1];
    for (int i = g_rowptr[n]; i < s1; ++i) {
        float sv = g_simp[i];
        if (sv == 0.f) continue;
        float w = expf(sv * irs);
        const float4* zc = (const float4*)(z + (size_t)g_colp[i] * 256);
        float4 b0 = zc[lane], b1 = zc[32 + lane];
        a0.x += w * b0.x; a0.y += w * b0.y; a0.z += w * b0.z; a0.w += w * b0.w;
        a1.x += w * b1.x; a1.y += w * b1.y; a1.z += w * b1.z; a1.w += w * b1.w;
    }
    if (act) {
        a0.x = a0.x > 0.f ? a0.x : 0.01f * a0.x;
        a0.y = a0.y > 0.f ? a0.y : 0.01f * a0.y;
        a0.z = a0.z > 0.f ? a0.z : 0.01f * a0.z;
        a0.w = a0.w > 0.f ? a0.w : 0.01f * a0.w;
        a1.x = a1.x > 0.f ? a1.x : 0.01f * a1.x;
        a1.y = a1.y > 0.f ? a1.y : 0.01f * a1.y;
        a1.z = a1.z > 0.f ? a1.z : 0.01f * a1.z;
        a1.w = a1.w > 0.f ? a1.w : 0.01f * a1.w;
    }
    float4* o = (float4*)(out + (size_t)n * 256);
    o[lane] = a0; o[32 + lane] = a1;
}

// aggregation, Hout = 16 (final layer, no activation)
__global__ void agg16_kernel(const float* __restrict__ z, float* __restrict__ out) {
    int n = (blockIdx.x * blockDim.x + threadIdx.x) >> 5;
    int lane = threadIdx.x & 31;
    if (n >= NNODES || lane >= 16) return;
    float acc = g_wself[n] * z[(size_t)n * 16 + lane];
    float irs = g_invrs[n];
    int s1 = g_rowptr[n + 1];
    for (int i = g_rowptr[n]; i < s1; ++i) {
        float sv = g_simp[i];
        if (sv == 0.f) continue;
        acc += expf(sv * irs) * z[(size_t)g_colp[i] * 16 + lane];
    }
    out[(size_t)n * 16 + lane] = acc;
}

// ---------------- host side ----------------
static void run_layer(const float* xin, int D, const float* W, int HIDp, int Hout,
                      float* outp, bool act, float* zp) {
    repack_kernel<<<(D * Hout + 255) / 256, 256>>>(W, D, Hout, HIDp);
    invn_kernel<<<(NNODES + 7) / 8, 256>>>(xin, D);
    sim_row_kernel<<<(NNODES + 7) / 8, 256>>>(xin, D);
    rownorm_kernel<<<(NNODES + 7) / 8, 256>>>();
    float* Bdev;
    cudaGetSymbolAddress((void**)&Bdev, g_B);
    if (Hout == 256) {
        dim3 grid(256 / 64, (NNODES + 127) / 128);
        mma_gemm_kernel<<<grid, 256>>>(xin, Bdev, zp, NNODES, D, 256);
        agg256_kernel<<<(NNODES + 7) / 8, 256>>>(zp, outp, act ? 1 : 0);
    } else {
        dim3 grid(1, (NNODES + 63) / 64);
        sgemm_kernel<64, 16, 16, 4, 1><<<grid, 256>>>(xin, Bdev, zp, NNODES, D, 16);
        agg16_kernel<<<(NNODES + 7) / 8, 256>>>(zp, outp);
    }
}

extern "C" void kernel_launch(void* const* d_in, const int* in_sizes, int n_in,
                              void* d_out, int out_size) {
    const float* x  = (const float*)d_in[0];
    const float* W0 = (const float*)d_in[1];
    const float* W1 = (const float*)d_in[2];
    const float* W2 = (const float*)d_in[3];
    const int*   row = (const int*)d_in[4];
    const int*   col = (const int*)d_in[5];
    float* out = (float*)d_out;

    float *zp, *h1p, *h2p;
    cudaGetSymbolAddress((void**)&zp,  g_z);
    cudaGetSymbolAddress((void**)&h1p, g_h1);
    cudaGetSymbolAddress((void**)&h2p, g_h2);

    // CSR build (recomputed every call; deterministic work)
    zero_cnt_kernel<<<(NNODES + 255) / 256, 256>>>();
    hist_kernel<<<(NEDGES + 255) / 256, 256>>>(row);
    scan_kernel<<<1, 1024>>>();
    scatter_kernel<<<(NEDGES + 255) / 256, 256>>>(row, col);

    // layer 0: D=128, W0[4,128,64] -> h1[N,256], leaky relu
    run_layer(x,   128, W0, 64, 256, h1p, true,  zp);
    // layer 1: D=256, W1[4,256,64] -> h2[N,256], leaky relu
    run_layer(h1p, 256, W1, 64, 256, h2p, true,  zp);
    // layer 2: D=256, W2[1,256,16] -> out[N,16], no activation
    run_layer(h2p, 256, W2, 16, 16,  out, false, zp);
}

// round 13
// speedup vs baseline: 1.5330x; 1.0148x over previous
#include <cuda_runtime.h>
#include <math.h>

#define NNODES 50000
#define NEDGES 800000

// ---------------- scratch (device globals: allocation-free) ----------------
__device__ int   g_cnt[NNODES];
__device__ int   g_cursor[NNODES];
__device__ int   g_rowptr[NNODES + 1];
__device__ int   g_colp[NEDGES];
__device__ float g_simp[NEDGES];
__device__ float g_invn[NNODES];
__device__ float g_invrs[NNODES];
__device__ float g_wself[NNODES];
__device__ float g_z [NNODES * 256];
__device__ float g_h1[NNODES * 256];
__device__ float g_h2[NNODES * 256];
__device__ float g_B [256 * 256];

// ---------------- CSR build ----------------
__global__ void zero_cnt_kernel() {
    int i = blockIdx.x * blockDim.x + threadIdx.x;
    if (i < NNODES) g_cnt[i] = 0;
}

__global__ void hist_kernel(const int* __restrict__ row) {
    int e = blockIdx.x * blockDim.x + threadIdx.x;
    if (e < NEDGES) atomicAdd(&g_cnt[row[e]], 1);
}

__global__ void scan_kernel() {
    __shared__ int wsum[32];
    __shared__ int carry;
    int tid = threadIdx.x, lane = tid & 31, wid = tid >> 5;
    if (tid == 0) { carry = 0; g_rowptr[0] = 0; }
    __syncthreads();
    for (int base = 0; base < NNODES; base += 1024) {
        int i = base + tid;
        int v = (i < NNODES) ? g_cnt[i] : 0;
        int s = v;
        #pragma unroll
        for (int o = 1; o < 32; o <<= 1) {
            int t = __shfl_up_sync(0xffffffffu, s, o);
            if (lane >= o) s += t;
        }
        if (lane == 31) wsum[wid] = s;
        __syncthreads();
        if (wid == 0) {
            int ws = wsum[lane];
            #pragma unroll
            for (int o = 1; o < 32; o <<= 1) {
                int t = __shfl_up_sync(0xffffffffu, ws, o);
                if (lane >= o) ws += t;
            }
            wsum[lane] = ws;
        }
        __syncthreads();
        int incl = s + (wid ? wsum[wid - 1] : 0) + carry;
        if (i < NNODES) { g_rowptr[i + 1] = incl; g_cursor[i] = incl - v; }
        __syncthreads();
        if (tid == 1023) carry = incl;
        __syncthreads();
    }
}

__global__ void scatter_kernel(const int* __restrict__ row, const int* __restrict__ col) {
    int e = blockIdx.x * blockDim.x + threadIdx.x;
    if (e >= NEDGES) return;
    int r = row[e];
    int pos = atomicAdd(&g_cursor[r], 1);
    g_colp[pos] = col[e];
}

// ---------------- per-layer kernels ----------------
// repack W[h, d, o] -> B[d, h*HID+o]  (dense [D x Hout] row-major)
__global__ void repack_kernel(const float* __restrict__ W, int D, int Hout, int HIDp) {
    int idx = blockIdx.x * blockDim.x + threadIdx.x;
    if (idx >= D * Hout) return;
    int d = idx / Hout, c = idx % Hout;
    int h = c / HIDp, o = c % HIDp;
    g_B[idx] = W[((size_t)h * D + d) * HIDp + o];
}

// 1 / max(||x_n||, 1e-12), warp per node
__global__ void invn_kernel(const float* __restrict__ x, int D) {
    int n = (blockIdx.x * blockDim.x + threadIdx.x) >> 5;
    int lane = threadIdx.x & 31;
    if (n >= NNODES) return;
    const float4* xr = (const float4*)(x + (size_t)n * D);
    int nq = D >> 2;
    float s = 0.f;
    for (int j = lane; j < nq; j += 32) {
        float4 a = xr[j];
        s += a.x * a.x + a.y * a.y + a.z * a.z + a.w * a.w;
    }
    #pragma unroll
    for (int o = 16; o; o >>= 1) s += __shfl_xor_sync(0xffffffffu, s, o);
    if (lane == 0) g_invn[n] = 1.f / fmaxf(sqrtf(s), 1e-12f);
}

// Row-stationary sim, 2-edge software pipeline (R9 winner, unchanged).
__global__ void sim_row_kernel(const float* __restrict__ x, int D) {
    int n = (blockIdx.x * blockDim.x + threadIdx.x) >> 5;
    int lane = threadIdx.x & 31;
    if (n >= NNODES) return;
    const float4* xr = (const float4*)(x + (size_t)n * D);
    float4 r0 = xr[lane];
    float4 r1 = make_float4(0.f, 0.f, 0.f, 0.f);
    if (D == 256) r1 = xr[32 + lane];
    float invn_n = g_invn[n];
    int i0 = g_rowptr[n], i1 = g_rowptr[n + 1];

    int i = i0;
    for (; i + 2 <= i1; i += 2) {
        int ca = g_colp[i], cb = g_colp[i + 1];
        const float4* xa = (const float4*)(x + (size_t)ca * D);
        const float4* xb = (const float4*)(x + (size_t)cb * D);
        float4 a0 = xa[lane];
        float4 b0 = xb[lane];
        float sa = r0.x * a0.x + r0.y * a0.y + r0.z * a0.z + r0.w * a0.w;
        float sb = r0.x * b0.x + r0.y * b0.y + r0.z * b0.z + r0.w * b0.w;
        if (D == 256) {
            float4 a1 = xa[32 + lane];
            float4 b1 = xb[32 + lane];
            sa += r1.x * a1.x + r1.y * a1.y + r1.z * a1.z + r1.w * a1.w;
            sb += r1.x * b1.x + r1.y * b1.y + r1.z * b1.z + r1.w * b1.w;
        }
        #pragma unroll
        for (int o = 16; o; o >>= 1) {
            sa += __shfl_xor_sync(0xffffffffu, sa, o);
            sb += __shfl_xor_sync(0xffffffffu, sb, o);
        }
        if (lane == 0) {
            sa *= invn_n * g_invn[ca];
            sb *= invn_n * g_invn[cb];
            g_simp[i]     = (sa < 0.1f) ? 0.f : sa;
            g_simp[i + 1] = (sb < 0.1f) ? 0.f : sb;
        }
    }
    if (i < i1) {
        int c = g_colp[i];
        const float4* xc = (const float4*)(x + (size_t)c * D);
        float4 b0 = xc[lane];
        float s = r0.x * b0.x + r0.y * b0.y + r0.z * b0.z + r0.w * b0.w;
        if (D == 256) {
            float4 b1 = xc[32 + lane];
            s += r1.x * b1.x + r1.y * b1.y + r1.z * b1.z + r1.w * b1.w;
        }
        #pragma unroll
        for (int o = 16; o; o >>= 1) s += __shfl_xor_sync(0xffffffffu, s, o);
        if (lane == 0) {
            s *= invn_n * g_invn[c];
            g_simp[i] = (s < 0.1f) ? 0.f : s;
        }
    }
}

// rowsum / degree / self weight, warp per node
__global__ void rownorm_kernel() {
    int n = (blockIdx.x * blockDim.x + threadIdx.x) >> 5;
    int lane = threadIdx.x & 31;
    if (n >= NNODES) return;
    int s0 = g_rowptr[n], s1 = g_rowptr[n + 1];
    float sum = 0.f;
    int cnt = 0;
    for (int i = s0 + lane; i < s1; i += 32) {
        float v = g_simp[i];
        sum += v;                 // v >= 0 (thresholded cosine), so |v| == v
        cnt += (v != 0.f);
    }
    #pragma unroll
    for (int o = 16; o; o >>= 1) {
        sum += __shfl_xor_sync(0xffffffffu, sum, o);
        cnt += __shfl_xor_sync(0xffffffffu, cnt, o);
    }
    if (lane == 0) {
        g_invrs[n] = (sum > 0.f) ? 1.f / sum : 0.f;
        g_wself[n] = expf(1.f / ((float)cnt + 1.f));
    }
}

// ---------------- 3xTF32 tensor-core GEMM (fp32-accurate) ----------------
__device__ __forceinline__ unsigned f2tf32(float f) {
    unsigned r;
    asm("cvt.rna.tf32.f32 %0, %1;" : "=r"(r) : "f"(f));
    return r;
}

__device__ __forceinline__ void mma_tf32(float c[4], unsigned a0, unsigned a1,
                                         unsigned a2, unsigned a3,
                                         unsigned b0, unsigned b1) {
    asm volatile(
        "mma.sync.aligned.m16n8k8.row.col.f32.tf32.tf32.f32 "
        "{%0,%1,%2,%3}, {%4,%5,%6,%7}, {%8,%9}, {%0,%1,%2,%3};"
        : "+f"(c[0]), "+f"(c[1]), "+f"(c[2]), "+f"(c[3])
        : "r"(a0), "r"(a1), "r"(a2), "r"(a3), "r"(b0), "r"(b1));
}

// C[M, Nc] = A[M, K] * B[K, Nc], BM=128 BN=64 BK=16, 8 warps (warp tile 32x32)
// (R9 serial schedule — frozen; both pipelined variants regressed.)
__global__ void __launch_bounds__(256)
mma_gemm_kernel(const float* __restrict__ A, const float* __restrict__ Bw,
                float* __restrict__ C, int M, int K, int Nc) {
    __shared__ unsigned AsHi[128][20];
    __shared__ unsigned AsLo[128][20];
    __shared__ unsigned BsHi[16][68];
    __shared__ unsigned BsLo[16][68];

    int tid = threadIdx.x;
    int lane = tid & 31, w = tid >> 5;
    int wm = w & 3, wn = w >> 2;       // 4 warps in M, 2 in N
    int g = lane >> 2, t = lane & 3;
    int rb = blockIdx.y * 128, cb = blockIdx.x * 64;

    float acc[2][4][4];
    #pragma unroll
    for (int mi = 0; mi < 2; mi++)
        #pragma unroll
        for (int ni = 0; ni < 4; ni++)
            #pragma unroll
            for (int j = 0; j < 4; j++) acc[mi][ni][j] = 0.f;

    for (int k0 = 0; k0 < K; k0 += 16) {
        // A tile 128x16 -> 512 float4, 2 per thread
        #pragma unroll
        for (int f = tid; f < 512; f += 256) {
            int r = f >> 2, kq = f & 3;
            int gr = rb + r;
            float4 v = make_float4(0.f, 0.f, 0.f, 0.f);
            if (gr < M) v = *(const float4*)&A[(size_t)gr * K + k0 + kq * 4];
            float vv[4] = {v.x, v.y, v.z, v.w};
            #pragma unroll
            for (int j = 0; j < 4; j++) {
                unsigned hi = f2tf32(vv[j]);
                AsHi[r][kq * 4 + j] = hi;
                AsLo[r][kq * 4 + j] = f2tf32(vv[j] - __uint_as_float(hi));
            }
        }
        // B tile 16x64 -> 256 float4, 1 per thread
        {
            int r = tid >> 4, nq = tid & 15;
            float4 v = *(const float4*)&Bw[(size_t)(k0 + r) * Nc + cb + nq * 4];
            float vv[4] = {v.x, v.y, v.z, v.w};
            #pragma unroll
            for (int j = 0; j < 4; j++) {
                unsigned hi = f2tf32(vv[j]);
                BsHi[r][nq * 4 + j] = hi;
                BsLo[r][nq * 4 + j] = f2tf32(vv[j] - __uint_as_float(hi));
            }
        }
        __syncthreads();

        #pragma unroll
        for (int kk = 0; kk < 16; kk += 8) {
            unsigned ah[2][4], al[2][4], bh[4][2], bl[4][2];
            #pragma unroll
            for (int mi = 0; mi < 2; mi++) {
                int r0 = wm * 32 + mi * 16 + g;
                ah[mi][0] = AsHi[r0][kk + t];     ah[mi][1] = AsHi[r0 + 8][kk + t];
                ah[mi][2] = AsHi[r0][kk + t + 4]; ah[mi][3] = AsHi[r0 + 8][kk + t + 4];
                al[mi][0] = AsLo[r0][kk + t];     al[mi][1] = AsLo[r0 + 8][kk + t];
                al[mi][2] = AsLo[r0][kk + t + 4]; al[mi][3] = AsLo[r0 + 8][kk + t + 4];
            }
            #pragma unroll
            for (int ni = 0; ni < 4; ni++) {
                int c0 = wn * 32 + ni * 8 + g;
                bh[ni][0] = BsHi[kk + t][c0]; bh[ni][1] = BsHi[kk + t + 4][c0];
                bl[ni][0] = BsLo[kk + t][c0]; bl[ni][1] = BsLo[kk + t + 4][c0];
            }
            #pragma unroll
            for (int mi = 0; mi < 2; mi++)
                #pragma unroll
                for (int ni = 0; ni < 4; ni++) {
                    // 3xTF32: hi*hi + hi*lo + lo*hi ~= fp32 product
                    mma_tf32(acc[mi][ni], ah[mi][0], ah[mi][1], ah[mi][2], ah[mi][3],
                             bh[ni][0], bh[ni][1]);
                    mma_tf32(acc[mi][ni], ah[mi][0], ah[mi][1], ah[mi][2], ah[mi][3],
                             bl[ni][0], bl[ni][1]);
                    mma_tf32(acc[mi][ni], al[mi][0], al[mi][1], al[mi][2], al[mi][3],
                             bh[ni][0], bh[ni][1]);
                }
        }
        __syncthreads();
    }

    #pragma unroll
    for (int mi = 0; mi < 2; mi++) {
        int row = rb + wm * 32 + mi * 16 + g;
        #pragma unroll
        for (int ni = 0; ni < 4; ni++) {
            int colc = cb + wn * 32 + ni * 8 + 2 * t;
            if (row < M)
                *(float2*)&C[(size_t)row * Nc + colc] =
                    make_float2(acc[mi][ni][0], acc[mi][ni][1]);
            if (row + 8 < M)
                *(float2*)&C[(size_t)(row + 8) * Nc + colc] =
                    make_float2(acc[mi][ni][2], acc[mi][ni][3]);
        }
    }
}

// plain tiled SGEMM (kept for the tiny N=16 final projection)
template <int BM, int BN, int BK, int TM, int TN>
__global__ void __launch_bounds__(256)
sgemm_kernel(const float* __restrict__ A, const float* __restrict__ Bw,
             float* __restrict__ C, int M, int K, int Nc) {
    static_assert((BM / TM) * (BN / TN) == 256, "grid of 256 threads");
    __shared__ float As[BK][BM + 4];
    __shared__ float Bs[BK][BN];
    constexpr int TCOLS = BN / TN;
    int tid = threadIdx.x;
    int tr = tid / TCOLS, tc = tid % TCOLS;
    int rb = blockIdx.y * BM, cb = blockIdx.x * BN;
    float acc[TM][TN];
    #pragma unroll
    for (int i = 0; i < TM; i++)
        #pragma unroll
        for (int j = 0; j < TN; j++) acc[i][j] = 0.f;

    for (int k0 = 0; k0 < K; k0 += BK) {
        for (int idx = tid; idx < BM * BK; idx += 256) {
            int r = idx / BK, c = idx % BK;
            int gr = rb + r;
            As[c][r] = (gr < M) ? A[(size_t)gr * K + k0 + c] : 0.f;
        }
        for (int idx = tid; idx < BK * BN; idx += 256) {
            int r = idx / BN, c = idx % BN;
            Bs[r][c] = Bw[(size_t)(k0 + r) * Nc + cb + c];
        }
        __syncthreads();
        #pragma unroll
        for (int k = 0; k < BK; k++) {
            float a[TM], b[TN];
            #pragma unroll
            for (int i = 0; i < TM; i++) a[i] = As[k][tr * TM + i];
            #pragma unroll
            for (int j = 0; j < TN; j++) b[j] = Bs[k][tc * TN + j];
            #pragma unroll
            for (int i = 0; i < TM; i++)
                #pragma unroll
                for (int j = 0; j < TN; j++) acc[i][j] += a[i] * b[j];
        }
        __syncthreads();
    }
    #pragma unroll
    for (int i = 0; i < TM; i++) {
        int gr = rb + tr * TM + i;
        if (gr < M) {
            #pragma unroll
            for (int j = 0; j < TN; j++)
                C[(size_t)gr * Nc + cb + tc * TN + j] = acc[i][j];
        }
    }
}

// aggregation, Hout = 256: warp per node, warp-cooperative weight scan.
// All 32 lanes load 32 edge weights + col indices in one coalesced load;
// ballot selects the ~13% surviving edges; only those do the z gather.
// Survivors processed in ascending edge order -> bit-identical summation.
__global__ void agg256_kernel(const float* __restrict__ z, float* __restrict__ out, int act) {
    int n = (blockIdx.x * blockDim.x + threadIdx.x) >> 5;
    int lane = threadIdx.x & 31;
    if (n >= NNODES) return;
    const float4* zr = (const float4*)(z + (size_t)n * 256);
    float ws = g_wself[n];
    float4 a0 = zr[lane], a1 = zr[32 + lane];
    a0.x *= ws; a0.y *= ws; a0.z *= ws; a0.w *= ws;
    a1.x *= ws; a1.y *= ws; a1.z *= ws; a1.w *= ws;
    float irs = g_invrs[n];
    int s0 = g_rowptr[n], s1 = g_rowptr[n + 1];
    for (int base = s0; base < s1; base += 32) {
        int idx = base + lane;
        float wv = 0.f;
        int cv = 0;
        if (idx < s1) { wv = g_simp[idx]; cv = g_colp[idx]; }
        unsigned m = __ballot_sync(0xffffffffu, wv != 0.f);
        while (m) {
            int j = __ffs(m) - 1;
            m &= m - 1;
            float sv = __shfl_sync(0xffffffffu, wv, j);
            int   cj = __shfl_sync(0xffffffffu, cv, j);
            float wj = expf(sv * irs);
            const float4* zc = (const float4*)(z + (size_t)cj * 256);
            float4 b0 = zc[lane], b1 = zc[32 + lane];
            a0.x += wj * b0.x; a0.y += wj * b0.y; a0.z += wj * b0.z; a0.w += wj * b0.w;
            a1.x += wj * b1.x; a1.y += wj * b1.y; a1.z += wj * b1.z; a1.w += wj * b1.w;
        }
    }
    if (act) {
        a0.x = a0.x > 0.f ? a0.x : 0.01f * a0.x;
        a0.y = a0.y > 0.f ? a0.y : 0.01f * a0.y;
        a0.z = a0.z > 0.f ? a0.z : 0.01f * a0.z;
        a0.w = a0.w > 0.f ? a0.w : 0.01f * a0.w;
        a1.x = a1.x > 0.f ? a1.x : 0.01f * a1.x;
        a1.y = a1.y > 0.f ? a1.y : 0.01f * a1.y;
        a1.z = a1.z > 0.f ? a1.z : 0.01f * a1.z;
        a1.w = a1.w > 0.f ? a1.w : 0.01f * a1.w;
    }
    float4* o = (float4*)(out + (size_t)n * 256);
    o[lane] = a0; o[32 + lane] = a1;
}

// aggregation, Hout = 16 (final layer, no activation), same ballot scheme.
__global__ void agg16_kernel(const float* __restrict__ z, float* __restrict__ out) {
    int n = (blockIdx.x * blockDim.x + threadIdx.x) >> 5;
    int lane = threadIdx.x & 31;
    if (n >= NNODES) return;
    float acc = 0.f;
    if (lane < 16) acc = g_wself[n] * z[(size_t)n * 16 + lane];
    float irs = g_invrs[n];
    int s0 = g_rowptr[n], s1 = g_rowptr[n + 1];
    for (int base = s0; base < s1; base += 32) {
        int idx = base + lane;
        float wv = 0.f;
        int cv = 0;
        if (idx < s1) { wv = g_simp[idx]; cv = g_colp[idx]; }
        unsigned m = __ballot_sync(0xffffffffu, wv != 0.f);
        while (m) {
            int j = __ffs(m) - 1;
            m &= m - 1;
            float sv = __shfl_sync(0xffffffffu, wv, j);
            int   cj = __shfl_sync(0xffffffffu, cv, j);
            if (lane < 16) acc += expf(sv * irs) * z[(size_t)cj * 16 + lane];
        }
    }
    if (lane < 16) out[(size_t)n * 16 + lane] = acc;
}

// ---------------- host side ----------------
static void run_layer(const float* xin, int D, const float* W, int HIDp, int Hout,
                      float* outp, bool act, float* zp) {
    repack_kernel<<<(D * Hout + 255) / 256, 256>>>(W, D, Hout, HIDp);
    invn_kernel<<<(NNODES + 7) / 8, 256>>>(xin, D);
    sim_row_kernel<<<(NNODES + 7) / 8, 256>>>(xin, D);
    rownorm_kernel<<<(NNODES + 7) / 8, 256>>>();
    float* Bdev;
    cudaGetSymbolAddress((void**)&Bdev, g_B);
    if (Hout == 256) {
        dim3 grid(256 / 64, (NNODES + 127) / 128);
        mma_gemm_kernel<<<grid, 256>>>(xin, Bdev, zp, NNODES, D, 256);
        agg256_kernel<<<(NNODES + 7) / 8, 256>>>(zp, outp, act ? 1 : 0);
    } else {
        dim3 grid(1, (NNODES + 63) / 64);
        sgemm_kernel<64, 16, 16, 4, 1><<<grid, 256>>>(xin, Bdev, zp, NNODES, D, 16);
        agg16_kernel<<<(NNODES + 7) / 8, 256>>>(zp, outp);
    }
}

extern "C" void kernel_launch(void* const* d_in, const int* in_sizes, int n_in,
                              void* d_out, int out_size) {
    const float* x  = (const float*)d_in[0];
    const float* W0 = (const float*)d_in[1];
    const float* W1 = (const float*)d_in[2];
    const float* W2 = (const float*)d_in[3];
    const int*   row = (const int*)d_in[4];
    const int*   col = (const int*)d_in[5];
    float* out = (float*)d_out;

    float *zp, *h1p, *h2p;
    cudaGetSymbolAddress((void**)&zp,  g_z);
    cudaGetSymbolAddress((void**)&h1p, g_h1);
    cudaGetSymbolAddress((void**)&h2p, g_h2);

    // CSR build (recomputed every call; deterministic work)
    zero_cnt_kernel<<<(NNODES + 255) / 256, 256>>>();
    hist_kernel<<<(NEDGES + 255) / 256, 256>>>(row);
    scan_kernel<<<1, 1024>>>();
    scatter_kernel<<<(NEDGES + 255) / 256, 256>>>(row, col);

    // layer 0: D=128, W0[4,128,64] -> h1[N,256], leaky relu
    run_layer(x,   128, W0, 64, 256, h1p, true,  zp);
    // layer 1: D=256, W1[4,256,64] -> h2[N,256], leaky relu
    run_layer(h1p, 256, W1, 64, 256, h2p, true,  zp);
    // layer 2: D=256, W2[1,256,16] -> out[N,16], no activation
    run_layer(h2p, 256, W2, 16, 16,  out, false, zp);
}